// round 8
// baseline (speedup 1.0000x reference)
#include <cuda_runtime.h>
#include <math.h>

#define D_MODEL 768
#define D_HID   3072
#define NUM_EXPERTS 8
#define NTOK    2048
#define NSLOT   (NTOK * 2)

// ---------------- device scratch (no runtime allocation allowed) ----------------
__device__ float g_hidden[NSLOT * D_HID];
__device__ float g_y[NSLOT * D_MODEL];
__device__ int   g_cnt[NUM_EXPERTS];
__device__ int   g_rows[NUM_EXPERTS * NTOK];
__device__ float g_wt[NSLOT];

// ---------------- reset ----------------------------------------------------------
__global__ void reset_kernel() {
    if (threadIdx.x < NUM_EXPERTS) g_cnt[threadIdx.x] = 0;
}

// ---------------- router (exact fp32; assignment must match reference) -----------
__global__ void router_kernel(const float* __restrict__ x,
                              const float* __restrict__ gw) {
    __shared__ float xs[D_MODEL];
    __shared__ float logits[NUM_EXPERTS];
    const int n = blockIdx.x;
    const float* xr = x + (size_t)n * D_MODEL;
    for (int i = threadIdx.x; i < D_MODEL; i += blockDim.x) xs[i] = xr[i];
    __syncthreads();

    const int w = threadIdx.x >> 5, lane = threadIdx.x & 31;
    if (w < NUM_EXPERTS) {
        float s = 0.f;
        for (int d = lane; d < D_MODEL; d += 32)
            s += xs[d] * gw[d * NUM_EXPERTS + w];
        #pragma unroll
        for (int o = 16; o; o >>= 1) s += __shfl_xor_sync(0xffffffffu, s, o);
        if (lane == 0) logits[w] = s;
    }
    __syncthreads();

    if (threadIdx.x == 0) {
        int i0 = 0; float l0 = logits[0];
        #pragma unroll
        for (int e = 1; e < NUM_EXPERTS; e++)
            if (logits[e] > l0) { l0 = logits[e]; i0 = e; }
        int i1 = -1; float l1 = -INFINITY;
        #pragma unroll
        for (int e = 0; e < NUM_EXPERTS; e++)
            if (e != i0 && logits[e] > l1) { l1 = logits[e]; i1 = e; }
        float e1 = expf(l1 - l0);
        float inv = 1.f / (1.f + e1);

        int p0 = atomicAdd(&g_cnt[i0], 1);
        g_rows[i0 * NTOK + p0] = n * 2 + 0;
        g_wt[n * 2 + 0] = inv;
        int p1 = atomicAdd(&g_cnt[i1], 1);
        g_rows[i1 * NTOK + p1] = n * 2 + 1;
        g_wt[n * 2 + 1] = e1 * inv;
    }
}

// ---------------- tf32 helpers --------------------------------------------------
__device__ __forceinline__ unsigned f2tf32(float f) {
    unsigned u;
    asm("cvt.rna.tf32.f32 %0, %1;" : "=r"(u) : "f"(f));
    return u;
}
__device__ __forceinline__ void mma_tf32(float* c, const unsigned* a,
                                         unsigned b0, unsigned b1) {
    asm volatile(
        "mma.sync.aligned.m16n8k8.row.col.f32.tf32.tf32.f32 "
        "{%0,%1,%2,%3}, {%4,%5,%6,%7}, {%8,%9}, {%0,%1,%2,%3};"
        : "+f"(c[0]), "+f"(c[1]), "+f"(c[2]), "+f"(c[3])
        : "r"(a[0]), "r"(a[1]), "r"(a[2]), "r"(a[3]), "r"(b0), "r"(b1));
}

// ---------------- grouped tensor-core GEMM: BM=128, BN=128, BK=16 ---------------
// 256 threads, 8 warps in 2(m)x4(n) grid; warp tile 64x32 (4 m-frags x 4 n-frags
// of m16n8k8 tf32). A staged in fragment-register order (one float4 per
// (kstep, mfrag, lane)) so operand fetch is 4x LDS.128 per k-step. B staged
// row-major with stride 136 (conflict-free scalar fetch, proven in R4).
template<bool GELU, bool HALVE_ROW>
__device__ __forceinline__ void gemm_tc(
    const float* __restrict__ A, int lda,
    const float* __restrict__ B, int ldb, int Kdim,
    const float* __restrict__ bias,
    float* __restrict__ C, int ldc)
{
    constexpr int BM = 128, BN = 128, BK = 16;
    constexpr int BSTR = BN + 8;    // banks (8k+n)%32 bijective over a warp

    const int e = blockIdx.z;
    const int cnt = g_cnt[e];
    const int m0 = blockIdx.y * BM;
    if (m0 >= cnt) return;
    const int n0 = blockIdx.x * BN;
    const int* rows = g_rows + e * NTOK;
    const float* Be = B + (size_t)e * Kdim * ldb;

    // APerm[s][mf][lane] : float4 = (a0,a1,a2,a3) of frag (s, mf) for lane
    __shared__ float4  As[2 * 8 * 32];
    __shared__ unsigned Bs[BK * BSTR];

    const int tid  = threadIdx.x;
    const int warp = tid >> 5;
    const int lane = tid & 31;
    const int grp  = lane >> 2;     // 0..7
    const int qid  = lane & 3;      // 0..3

    const int warp_m = warp & 1;    // rows warp_m*64 .. +63
    const int warp_n = warp >> 1;   // cols warp_n*32 .. +31
    const int cbase  = warp_n * 32;

    // ---- A staging mapping: thread t handles row = t>>1, two float4s:
    //      it=0 -> k[0..7) half hb=t&1 of s=0 ; it=1 -> same half of s=1
    const int arow = tid >> 1;
    const int hb   = tid & 1;
    const int amf  = arow >> 4;
    const int agrp = arow & 7;
    const int arb  = (arow >> 3) & 1;
    const int gr   = m0 + arow;
    const bool avalid = gr < cnt;
    const float* aptr = A;
    if (avalid) {
        int slot = rows[gr];
        int src  = HALVE_ROW ? (slot >> 1) : slot;
        aptr = A + (size_t)src * lda;
    }
    // float* view of As for scattered stores
    float* AsF = (float*)As;

    // ---- B staging: 16x128, 2 float4/thread (rows bk0 and bk0+8)
    const int bk0 = tid >> 5;
    const int bn4 = lane * 4;
    const float* bptr0 = Be + (size_t)bk0 * ldb + n0 + bn4;
    const float* bptr1 = bptr0 + (size_t)8 * ldb;

    float acc[4][4][4];
    #pragma unroll
    for (int i = 0; i < 4; i++)
        #pragma unroll
        for (int j = 0; j < 4; j++)
            #pragma unroll
            for (int q = 0; q < 4; q++) acc[i][j][q] = 0.f;

    const int ktiles = Kdim / BK;

    // prologue: stage tile 0 into registers
    float4 a_st0, a_st1, b_st0, b_st1;
    {
        a_st0 = avalid ? *(const float4*)(aptr + hb * 4)
                       : make_float4(0.f, 0.f, 0.f, 0.f);
        a_st1 = avalid ? *(const float4*)(aptr + hb * 4 + 8)
                       : make_float4(0.f, 0.f, 0.f, 0.f);
        b_st0 = *(const float4*)(bptr0);
        b_st1 = *(const float4*)(bptr1);
    }

    for (int t = 0; t < ktiles; t++) {
        __syncthreads();
        // commit staged tile (tf32-rounded)
        {
            // A: scatter 4 values of each float4 to 4 lanes' slots
            int base0 = ((0 * 8 + amf) * 32 + agrp * 4) * 4 + hb * 2 + arb;
            AsF[base0 +  0] = __uint_as_float(f2tf32(a_st0.x));
            AsF[base0 +  4] = __uint_as_float(f2tf32(a_st0.y));
            AsF[base0 +  8] = __uint_as_float(f2tf32(a_st0.z));
            AsF[base0 + 12] = __uint_as_float(f2tf32(a_st0.w));
            int base1 = ((1 * 8 + amf) * 32 + agrp * 4) * 4 + hb * 2 + arb;
            AsF[base1 +  0] = __uint_as_float(f2tf32(a_st1.x));
            AsF[base1 +  4] = __uint_as_float(f2tf32(a_st1.y));
            AsF[base1 +  8] = __uint_as_float(f2tf32(a_st1.z));
            AsF[base1 + 12] = __uint_as_float(f2tf32(a_st1.w));
            uint4 bv0 = make_uint4(f2tf32(b_st0.x), f2tf32(b_st0.y),
                                   f2tf32(b_st0.z), f2tf32(b_st0.w));
            *(uint4*)&Bs[bk0 * BSTR + bn4] = bv0;
            uint4 bv1 = make_uint4(f2tf32(b_st1.x), f2tf32(b_st1.y),
                                   f2tf32(b_st1.z), f2tf32(b_st1.w));
            *(uint4*)&Bs[(bk0 + 8) * BSTR + bn4] = bv1;
        }
        __syncthreads();
        // prefetch next tile
        if (t + 1 < ktiles) {
            int k0 = (t + 1) * BK;
            a_st0 = avalid ? *(const float4*)(aptr + k0 + hb * 4)
                           : make_float4(0.f, 0.f, 0.f, 0.f);
            a_st1 = avalid ? *(const float4*)(aptr + k0 + hb * 4 + 8)
                           : make_float4(0.f, 0.f, 0.f, 0.f);
            b_st0 = *(const float4*)(bptr0 + (size_t)k0 * ldb);
            b_st1 = *(const float4*)(bptr1 + (size_t)k0 * ldb);
        }
        // compute 2 k-steps of 8
        #pragma unroll
        for (int s = 0; s < 2; s++) {
            unsigned a[4][4];
            #pragma unroll
            for (int i = 0; i < 4; i++) {
                float4 v = As[(s * 8 + warp_m * 4 + i) * 32 + lane];
                a[i][0] = __float_as_uint(v.x);
                a[i][1] = __float_as_uint(v.y);
                a[i][2] = __float_as_uint(v.z);
                a[i][3] = __float_as_uint(v.w);
            }
            const int ks = s * 8;
            unsigned b[4][2];
            #pragma unroll
            for (int j = 0; j < 4; j++) {
                int nc = cbase + j * 8 + grp;
                b[j][0] = Bs[(ks + qid) * BSTR + nc];
                b[j][1] = Bs[(ks + qid + 4) * BSTR + nc];
            }
            #pragma unroll
            for (int j = 0; j < 4; j++)
                #pragma unroll
                for (int i = 0; i < 4; i++)
                    mma_tf32(acc[i][j], a[i], b[j][0], b[j][1]);
        }
    }

    // epilogue: bias (+ GELU), scatter rows via slot ids
    const float* bp = bias + (size_t)e * ldc;
    float2 bv[4];
    #pragma unroll
    for (int j = 0; j < 4; j++) {
        int c = n0 + cbase + j * 8 + 2 * qid;
        bv[j] = *(const float2*)(bp + c);
    }
    #pragma unroll
    for (int i = 0; i < 4; i++) {
        int rbase = m0 + warp_m * 64 + i * 16 + grp;
        #pragma unroll
        for (int h = 0; h < 2; h++) {       // c0/c1 (row) vs c2/c3 (row+8)
            int r = rbase + h * 8;
            if (r < cnt) {
                int slot = rows[r];
                float* crow = C + (size_t)slot * ldc;
                #pragma unroll
                for (int j = 0; j < 4; j++) {
                    int c = n0 + cbase + j * 8 + 2 * qid;
                    float v0 = acc[i][j][2 * h + 0] + bv[j].x;
                    float v1 = acc[i][j][2 * h + 1] + bv[j].y;
                    if (GELU) {
                        v0 = 0.5f * v0 * (1.f + erff(v0 * 0.70710678118654752f));
                        v1 = 0.5f * v1 * (1.f + erff(v1 * 0.70710678118654752f));
                    }
                    *(float2*)(crow + c) = make_float2(v0, v1);
                }
            }
        }
    }
}

__global__ void __launch_bounds__(256, 2)
gemm1_kernel(const float* __restrict__ x, const float* __restrict__ w1,
             const float* __restrict__ b1) {
    gemm_tc<true, true>(x, D_MODEL, w1, D_HID, D_MODEL, b1, g_hidden, D_HID);
}

__global__ void __launch_bounds__(256, 2)
gemm2_kernel(const float* __restrict__ w2, const float* __restrict__ b2) {
    gemm_tc<false, false>(g_hidden, D_HID, w2, D_MODEL, D_HID, b2, g_y, D_MODEL);
}

// ---------------- weighted combine ----------------------------------------------
__global__ void combine_kernel(float* __restrict__ out) {
    int idx = blockIdx.x * blockDim.x + threadIdx.x;
    int n  = idx / (D_MODEL / 4);
    int d4 = (idx % (D_MODEL / 4)) * 4;
    float w0 = g_wt[2 * n], w1 = g_wt[2 * n + 1];
    float4 y0 = *(const float4*)&g_y[(size_t)(2 * n + 0) * D_MODEL + d4];
    float4 y1 = *(const float4*)&g_y[(size_t)(2 * n + 1) * D_MODEL + d4];
    float4 o;
    o.x = w0 * y0.x + w1 * y1.x;
    o.y = w0 * y0.y + w1 * y1.y;
    o.z = w0 * y0.z + w1 * y1.z;
    o.w = w0 * y0.w + w1 * y1.w;
    *(float4*)&out[(size_t)n * D_MODEL + d4] = o;
}

// ---------------- launcher -------------------------------------------------------
extern "C" void kernel_launch(void* const* d_in, const int* in_sizes, int n_in,
                              void* d_out, int out_size) {
    const float* x      = (const float*)d_in[0];
    const float* gate_w = (const float*)d_in[1];
    const float* w1     = (const float*)d_in[2];
    const float* b1     = (const float*)d_in[3];
    const float* w2     = (const float*)d_in[4];
    const float* b2     = (const float*)d_in[5];
    float* out = (float*)d_out;

    reset_kernel<<<1, 32>>>();
    router_kernel<<<NTOK, 256>>>(x, gate_w);
    gemm1_kernel<<<dim3(D_HID / 128, NTOK / 128, NUM_EXPERTS), 256>>>(x, w1, b1);
    gemm2_kernel<<<dim3(D_MODEL / 128, NTOK / 128, NUM_EXPERTS), 256>>>(w2, b2);
    combine_kernel<<<(NTOK * (D_MODEL / 4)) / 256, 256>>>(out);
}

// round 10
// speedup vs baseline: 1.8289x; 1.8289x over previous
#include <cuda_runtime.h>
#include <math.h>
#include <stdint.h>

#define D_MODEL 768
#define D_HID   3072
#define NUM_EXPERTS 8
#define NTOK    2048
#define NSLOT   (NTOK * 2)

// ---------------- device scratch (no runtime allocation allowed) ----------------
__device__ float g_hidden[NSLOT * D_HID];
__device__ float g_y[NSLOT * D_MODEL];
__device__ int   g_cnt[NUM_EXPERTS];
__device__ int   g_rows[NUM_EXPERTS * NTOK];
__device__ float g_wt[NSLOT];

// ---------------- reset ----------------------------------------------------------
__global__ void reset_kernel() {
    if (threadIdx.x < NUM_EXPERTS) g_cnt[threadIdx.x] = 0;
}

// ---------------- router (exact fp32; assignment must match reference) -----------
__global__ void router_kernel(const float* __restrict__ x,
                              const float* __restrict__ gw) {
    __shared__ float xs[D_MODEL];
    __shared__ float logits[NUM_EXPERTS];
    const int n = blockIdx.x;
    const float* xr = x + (size_t)n * D_MODEL;
    for (int i = threadIdx.x; i < D_MODEL; i += blockDim.x) xs[i] = xr[i];
    __syncthreads();

    const int w = threadIdx.x >> 5, lane = threadIdx.x & 31;
    if (w < NUM_EXPERTS) {
        float s = 0.f;
        for (int d = lane; d < D_MODEL; d += 32)
            s += xs[d] * gw[d * NUM_EXPERTS + w];
        #pragma unroll
        for (int o = 16; o; o >>= 1) s += __shfl_xor_sync(0xffffffffu, s, o);
        if (lane == 0) logits[w] = s;
    }
    __syncthreads();

    if (threadIdx.x == 0) {
        int i0 = 0; float l0 = logits[0];
        #pragma unroll
        for (int e = 1; e < NUM_EXPERTS; e++)
            if (logits[e] > l0) { l0 = logits[e]; i0 = e; }
        int i1 = -1; float l1 = -INFINITY;
        #pragma unroll
        for (int e = 0; e < NUM_EXPERTS; e++)
            if (e != i0 && logits[e] > l1) { l1 = logits[e]; i1 = e; }
        float e1 = expf(l1 - l0);
        float inv = 1.f / (1.f + e1);

        int p0 = atomicAdd(&g_cnt[i0], 1);
        g_rows[i0 * NTOK + p0] = n * 2 + 0;
        g_wt[n * 2 + 0] = inv;
        int p1 = atomicAdd(&g_cnt[i1], 1);
        g_rows[i1 * NTOK + p1] = n * 2 + 1;
        g_wt[n * 2 + 1] = e1 * inv;
    }
}

// ---------------- tf32 helpers --------------------------------------------------
__device__ __forceinline__ unsigned f2tf32(float f) {
    unsigned u;
    asm("cvt.rna.tf32.f32 %0, %1;" : "=r"(u) : "f"(f));
    return u;
}
__device__ __forceinline__ void mma_tf32(float* c,
                                         unsigned a0, unsigned a1, unsigned a2, unsigned a3,
                                         unsigned b0, unsigned b1) {
    asm volatile(
        "mma.sync.aligned.m16n8k8.row.col.f32.tf32.tf32.f32 "
        "{%0,%1,%2,%3}, {%4,%5,%6,%7}, {%8,%9}, {%0,%1,%2,%3};"
        : "+f"(c[0]), "+f"(c[1]), "+f"(c[2]), "+f"(c[3])
        : "r"(a0), "r"(a1), "r"(a2), "r"(a3), "r"(b0), "r"(b1));
}

// ---------------- grouped tensor-core GEMM: BM=64, BN=128, BK=32 ----------------
// 8 warps in 2(m)x4(n); warp tile 32x32 (2 m-frags x 4 n-frags of m16n8k8 tf32).
// Double-buffered smem, ONE __syncthreads per k32 tile: STS for tile t+1 targets
// the idle buffer while MMAs consume tile t. Layouts are R4's proven
// conflict-free patterns (A pad: (4*row+k)%32 bijective; B stride 136).
static constexpr int BM = 64, BN = 128, BK = 32;
static constexpr int ASTR = BK + 4;   // 36
static constexpr int BSTR = BN + 8;   // 136
static constexpr int SZ_A = BM * ASTR;            // floats per A buffer (2304)
static constexpr int SZ_B = BK * BSTR;            // words per B buffer (4352)
static constexpr int OFF_A    = 0;                // 2 buffers: 2*9216 B
static constexpr int OFF_B    = 2 * SZ_A * 4;     // 18432; 2 buffers: 2*17408 B
static constexpr int OFF_SLOT = OFF_B + 2 * SZ_B * 4;   // 53248
static constexpr int SMEM_TOTAL = OFF_SLOT + BM * 4;    // 53504

template<bool GELU, bool HALVE_ROW>
__device__ __forceinline__ void gemm_tc(
    const float* __restrict__ A, int lda,
    const float* __restrict__ B, int ldb, int Kdim,
    const float* __restrict__ bias,
    float* __restrict__ C, int ldc)
{
    const int e = blockIdx.z;
    const int cnt = g_cnt[e];
    const int m0 = blockIdx.y * BM;
    if (m0 >= cnt) return;
    const int n0 = blockIdx.x * BN;
    const int* rows = g_rows + e * NTOK;
    const float* Be = B + (size_t)e * Kdim * ldb;

    extern __shared__ char sm[];
    unsigned* AsAll = (unsigned*)(sm + OFF_A);
    unsigned* BsAll = (unsigned*)(sm + OFF_B);
    int* slotSm = (int*)(sm + OFF_SLOT);

    const int tid  = threadIdx.x;
    const int warp = tid >> 5;
    const int lane = tid & 31;
    const int grp  = lane >> 2;     // 0..7
    const int qid  = lane & 3;      // 0..3

    const int warp_m = warp & 1;    // rows warp_m*32 .. +31
    const int warp_n = warp >> 1;   // cols warp_n*32 .. +31
    const int cbase  = warp_n * 32;

    if (tid < BM) {
        int gr = m0 + tid;
        slotSm[tid] = (gr < cnt) ? rows[gr] : -1;
    }
    __syncthreads();

    // ---- A staging: 64 rows x 32 k = 512 float4; thread handles ids tid, tid+256
    //      id -> row = id>>3 (coalesced 128B per 8 threads), kq = id&7
    const int ar0 = tid >> 3, ar1 = ar0 + 32, akq = tid & 7;
    const int sl0 = slotSm[ar0], sl1 = slotSm[ar1];
    const bool av0 = sl0 >= 0, av1 = sl1 >= 0;
    const float* ap0 = A + (av0 ? (size_t)(HALVE_ROW ? (sl0 >> 1) : sl0) * lda : 0) + akq * 4;
    const float* ap1 = A + (av1 ? (size_t)(HALVE_ROW ? (sl1 >> 1) : sl1) * lda : 0) + akq * 4;

    // ---- B staging: 32 rows x 128 cols = 1024 float4; 4 per thread
    //      it -> row = (tid>>5) + it*8, col = lane*4
    const int brow = tid >> 5;
    const int bc   = lane * 4;
    const float* bp = Be + (size_t)brow * ldb + n0 + bc;

    float4 apf0, apf1, bpf[4];

    const int T = Kdim / BK;

    // register prefetch of tile (k0)
    auto pf = [&](int k0) {
        apf0 = av0 ? *(const float4*)(ap0 + k0) : make_float4(0.f, 0.f, 0.f, 0.f);
        apf1 = av1 ? *(const float4*)(ap1 + k0) : make_float4(0.f, 0.f, 0.f, 0.f);
        #pragma unroll
        for (int it = 0; it < 4; it++)
            bpf[it] = *(const float4*)(bp + (size_t)(k0 + it * 8) * ldb);
    };
    // commit prefetched regs (tf32-rounded) to smem buffer `buf`
    auto sts = [&](int buf) {
        unsigned* Asb = AsAll + buf * SZ_A;
        unsigned* Bsb = BsAll + buf * SZ_B;
        uint4 a0 = make_uint4(f2tf32(apf0.x), f2tf32(apf0.y), f2tf32(apf0.z), f2tf32(apf0.w));
        *(uint4*)&Asb[ar0 * ASTR + akq * 4] = a0;
        uint4 a1 = make_uint4(f2tf32(apf1.x), f2tf32(apf1.y), f2tf32(apf1.z), f2tf32(apf1.w));
        *(uint4*)&Asb[ar1 * ASTR + akq * 4] = a1;
        #pragma unroll
        for (int it = 0; it < 4; it++) {
            uint4 bv = make_uint4(f2tf32(bpf[it].x), f2tf32(bpf[it].y),
                                  f2tf32(bpf[it].z), f2tf32(bpf[it].w));
            *(uint4*)&Bsb[(brow + it * 8) * BSTR + bc] = bv;
        }
    };

    float acc[2][4][4];
    #pragma unroll
    for (int i = 0; i < 2; i++)
        #pragma unroll
        for (int j = 0; j < 4; j++)
            #pragma unroll
            for (int q = 0; q < 4; q++) acc[i][j][q] = 0.f;

    // prologue: tile0 -> buf0, prefetch tile1
    pf(0);
    sts(0);
    pf(BK);

    for (int t = 0; t < T; t++) {
        __syncthreads();    // buf[t&1] ready; prior reads of buf[(t+1)&1] done
        if (t + 1 < T) {
            sts((t + 1) & 1);               // overlaps with MMAs below (no barrier)
            if (t + 2 < T) pf((t + 2) * BK);
        }
        const unsigned* Asb = AsAll + (t & 1) * SZ_A;
        const unsigned* Bsb = BsAll + (t & 1) * SZ_B;
        #pragma unroll
        for (int ks = 0; ks < 4; ks++) {
            const int k8 = ks * 8;
            unsigned a[2][4];
            #pragma unroll
            for (int i = 0; i < 2; i++) {
                int mr = warp_m * 32 + i * 16 + grp;
                a[i][0] = Asb[mr * ASTR + k8 + qid];
                a[i][1] = Asb[(mr + 8) * ASTR + k8 + qid];
                a[i][2] = Asb[mr * ASTR + k8 + qid + 4];
                a[i][3] = Asb[(mr + 8) * ASTR + k8 + qid + 4];
            }
            unsigned b[4][2];
            #pragma unroll
            for (int j = 0; j < 4; j++) {
                int nc = cbase + j * 8 + grp;
                b[j][0] = Bsb[(k8 + qid) * BSTR + nc];
                b[j][1] = Bsb[(k8 + qid + 4) * BSTR + nc];
            }
            #pragma unroll
            for (int j = 0; j < 4; j++)
                #pragma unroll
                for (int i = 0; i < 2; i++)
                    mma_tf32(acc[i][j], a[i][0], a[i][1], a[i][2], a[i][3],
                             b[j][0], b[j][1]);
        }
    }

    // epilogue: bias (+ GELU), scatter rows via slot ids
    const float* bpb = bias + (size_t)e * ldc;
    float2 bv[4];
    #pragma unroll
    for (int j = 0; j < 4; j++) {
        int c = n0 + cbase + j * 8 + 2 * qid;
        bv[j] = *(const float2*)(bpb + c);
    }
    #pragma unroll
    for (int i = 0; i < 2; i++) {
        int lbase = warp_m * 32 + i * 16 + grp;
        #pragma unroll
        for (int h = 0; h < 2; h++) {       // c0/c1 (row) vs c2/c3 (row+8)
            int lr = lbase + h * 8;
            int slot = slotSm[lr];
            if (slot >= 0) {
                float* crow = C + (size_t)slot * ldc;
                #pragma unroll
                for (int j = 0; j < 4; j++) {
                    int c = n0 + cbase + j * 8 + 2 * qid;
                    float v0 = acc[i][j][2 * h + 0] + bv[j].x;
                    float v1 = acc[i][j][2 * h + 1] + bv[j].y;
                    if (GELU) {
                        v0 = 0.5f * v0 * (1.f + erff(v0 * 0.70710678118654752f));
                        v1 = 0.5f * v1 * (1.f + erff(v1 * 0.70710678118654752f));
                    }
                    *(float2*)(crow + c) = make_float2(v0, v1);
                }
            }
        }
    }
}

__global__ void __launch_bounds__(256, 2)
gemm1_kernel(const float* __restrict__ x, const float* __restrict__ w1,
             const float* __restrict__ b1) {
    gemm_tc<true, true>(x, D_MODEL, w1, D_HID, D_MODEL, b1, g_hidden, D_HID);
}

__global__ void __launch_bounds__(256, 2)
gemm2_kernel(const float* __restrict__ w2, const float* __restrict__ b2) {
    gemm_tc<false, false>(g_hidden, D_HID, w2, D_MODEL, D_HID, b2, g_y, D_MODEL);
}

// ---------------- weighted combine ----------------------------------------------
__global__ void combine_kernel(float* __restrict__ out) {
    int idx = blockIdx.x * blockDim.x + threadIdx.x;
    int n  = idx / (D_MODEL / 4);
    int d4 = (idx % (D_MODEL / 4)) * 4;
    float w0 = g_wt[2 * n], w1 = g_wt[2 * n + 1];
    float4 y0 = *(const float4*)&g_y[(size_t)(2 * n + 0) * D_MODEL + d4];
    float4 y1 = *(const float4*)&g_y[(size_t)(2 * n + 1) * D_MODEL + d4];
    float4 o;
    o.x = w0 * y0.x + w1 * y1.x;
    o.y = w0 * y0.y + w1 * y1.y;
    o.z = w0 * y0.z + w1 * y1.z;
    o.w = w0 * y0.w + w1 * y1.w;
    *(float4*)&out[(size_t)n * D_MODEL + d4] = o;
}

// ---------------- launcher -------------------------------------------------------
extern "C" void kernel_launch(void* const* d_in, const int* in_sizes, int n_in,
                              void* d_out, int out_size) {
    const float* x      = (const float*)d_in[0];
    const float* gate_w = (const float*)d_in[1];
    const float* w1     = (const float*)d_in[2];
    const float* b1     = (const float*)d_in[3];
    const float* w2     = (const float*)d_in[4];
    const float* b2     = (const float*)d_in[5];
    float* out = (float*)d_out;

    cudaFuncSetAttribute(gemm1_kernel, cudaFuncAttributeMaxDynamicSharedMemorySize, SMEM_TOTAL);
    cudaFuncSetAttribute(gemm2_kernel, cudaFuncAttributeMaxDynamicSharedMemorySize, SMEM_TOTAL);

    reset_kernel<<<1, 32>>>();
    router_kernel<<<NTOK, 256>>>(x, gate_w);
    gemm1_kernel<<<dim3(D_HID / BN, NTOK / BM, NUM_EXPERTS), 256, SMEM_TOTAL>>>(x, w1, b1);
    gemm2_kernel<<<dim3(D_MODEL / BN, NTOK / BM, NUM_EXPERTS), 256, SMEM_TOTAL>>>(w2, b2);
    combine_kernel<<<(NTOK * (D_MODEL / 4)) / 256, 256>>>(out);
}